// round 17
// baseline (speedup 1.0000x reference)
#include <cuda_runtime.h>
#include <cuda_fp16.h>
#include <cstdint>

#define B_   16
#define S_   512
#define H_   128
#define L_   20
#define TM   128          // s per tile
#define TT   32           // t per tile
#define NROWS 80          // 4 t x 20 l rows per chunk
#define STRDH 136         // smem row stride (halves): 272B, conflict-free ldmatrix
#define R1STR 22          // r1 smem stride (floats)
#define NCTA 296          // 2 persistent CTAs per SM x 148 SMs
#define NTILES 1024       // (16 b x 16 t x 4 s)
#define NJOBS (NTILES * 8)

// smem halves layout: A + 3-deep B ring + r1
#define NH_A   (TM * STRDH)            // 17408
#define NH_BUF (NROWS * STRDH)         // 10880 per buffer
#define OFFH_B0 NH_A
#define OFFH_R1 (NH_A + 3 * NH_BUF)    // 50048 halves -> byte 100096 (16-aligned)
#define SMEM_BYTES (OFFH_R1 * 2 + TM * R1STR * 4)   // 111360 -> 2 CTAs/SM

// precomputed operands in HBM
__device__ __half g_A[B_ * S_ * H_];              // fp16(v1)                2 MB
__device__ __half g_B[(size_t)B_ * S_ * L_ * H_]; // fp16(v2 * w^2 * r2)  41.9 MB
__device__ float  g_r1[B_ * L_ * S_];

static __device__ __forceinline__ uint32_t f16x2(float lo, float hi) {
    uint32_t r;
    asm("cvt.rn.f16x2.f32 %0, %1, %2;" : "=r"(r) : "f"(hi), "f"(lo));
    return r;
}
static __device__ __forceinline__ void mma_f16(float& c0, float& c1, float& c2, float& c3,
                                               uint32_t a0, uint32_t a1, uint32_t a2, uint32_t a3,
                                               uint32_t b0, uint32_t b1) {
    asm volatile("mma.sync.aligned.m16n8k16.row.col.f32.f16.f16.f32 "
                 "{%0,%1,%2,%3}, {%4,%5,%6,%7}, {%8,%9}, {%0,%1,%2,%3};"
                 : "+f"(c0), "+f"(c1), "+f"(c2), "+f"(c3)
                 : "r"(a0), "r"(a1), "r"(a2), "r"(a3), "r"(b0), "r"(b1));
}
static __device__ __forceinline__ void ldsm4(uint32_t& r0, uint32_t& r1, uint32_t& r2, uint32_t& r3,
                                             uint32_t addr) {
    asm volatile("ldmatrix.sync.aligned.m8n8.x4.shared.b16 {%0,%1,%2,%3}, [%4];"
                 : "=r"(r0), "=r"(r1), "=r"(r2), "=r"(r3) : "r"(addr));
}
static __device__ __forceinline__ void ldsm2(uint32_t& r0, uint32_t& r1, uint32_t addr) {
    asm volatile("ldmatrix.sync.aligned.m8n8.x2.shared.b16 {%0,%1}, [%2];"
                 : "=r"(r0), "=r"(r1) : "r"(addr));
}
static __device__ __forceinline__ uint32_t smem_u32(const void* p) {
    return (uint32_t)__cvta_generic_to_shared(p);
}
static __device__ __forceinline__ void cp16cg(uint32_t dst, const void* src) {
    asm volatile("cp.async.cg.shared.global [%0], [%1], 16;" :: "r"(dst), "l"(src) : "memory");
}
#define CP_COMMIT() asm volatile("cp.async.commit_group;" ::: "memory")
#define CP_WAIT1()  asm volatile("cp.async.wait_group 1;" ::: "memory")
#define CP_WAIT0()  asm volatile("cp.async.wait_group 0;" ::: "memory")

// ---------------- kernel 1: norms + operand prep (fused) ----------------
__global__ void prep_kernel(const float* __restrict__ v1, const float* __restrict__ v2,
                            const float* __restrict__ w) {
    const int which = blockIdx.y;
    const float* v  = which ? v2 : v1;
    const int gwarp = (blockIdx.x * blockDim.x + threadIdx.x) >> 5;
    const int lane  = threadIdx.x & 31;
    if (gwarp >= B_ * S_) return;

    const float4 xv = ((const float4*)(v + (size_t)gwarp * H_))[lane];

    if (!which) {
        uint2 o;
        o.x = f16x2(xv.x, xv.y);
        o.y = f16x2(xv.z, xv.w);
        *(uint2*)&g_A[(size_t)gwarp * H_ + lane * 4] = o;
    }
    const int b = gwarp >> 9;
    const int s = gwarp & (S_ - 1);

    #pragma unroll
    for (int l = 0; l < L_; l += 4) {
        float4 wv[4];
        float  p[4];
        #pragma unroll
        for (int q = 0; q < 4; ++q) {
            wv[q] = ((const float4*)(w + (l + q) * H_))[lane];
            float t;
            t = wv[q].x * xv.x; p[q]  = t * t;
            t = wv[q].y * xv.y; p[q] += t * t;
            t = wv[q].z * xv.z; p[q] += t * t;
            t = wv[q].w * xv.w; p[q] += t * t;
        }
        #pragma unroll
        for (int o = 16; o; o >>= 1) {
            #pragma unroll
            for (int q = 0; q < 4; ++q)
                p[q] += __shfl_xor_sync(0xffffffffu, p[q], o);
        }
        float r[4];
        #pragma unroll
        for (int q = 0; q < 4; ++q) r[q] = rsqrtf(fmaxf(p[q], 1e-24f));

        if (!which) {
            if (lane == 0) {
                #pragma unroll
                for (int q = 0; q < 4; ++q)
                    g_r1[((size_t)b * L_ + l + q) * S_ + s] = r[q];
            }
        } else {
            #pragma unroll
            for (int q = 0; q < 4; ++q) {
                uint2 o;
                o.x = f16x2(xv.x * wv[q].x * wv[q].x * r[q], xv.y * wv[q].y * wv[q].y * r[q]);
                o.y = f16x2(xv.z * wv[q].z * wv[q].z * r[q], xv.w * wv[q].w * wv[q].w * r[q]);
                *(uint2*)&g_B[((size_t)gwarp * L_ + l + q) * H_ + lane * 4] = o;
            }
        }
    }
}

// ---------------- kernel 2: persistent fp16 GEMM over chunk-jobs ----------------
// 296 persistent CTAs; job = tile*8 + chunk; tile = ((b*16 + t)*4 + s).
// CTA k owns the contiguous job range [k*NJOBS/NCTA, (k+1)*NJOBS/NCTA).
// B 3-ring keyed by global job index; A/r1 reloaded only at tile boundaries.
__global__ void __launch_bounds__(256, 2)
match_kernel(float* __restrict__ out) {
    extern __shared__ char smc[];
    __half* sm  = (__half*)smc;
    float*  sR1 = (float*)(smc + OFFH_R1 * 2);   // [128][R1STR] r1 transposed

    const int tid  = threadIdx.x;
    const int wid  = tid >> 5;
    const int lane = tid & 31;

    const int warp_m = wid >> 1;   // 0..3
    const int warp_n = wid & 1;    // 0..1
    const int grp    = lane >> 2;  // 0..7
    const int thr4   = lane & 3;   // 0..3

    const uint32_t sm_u = smem_u32(sm);

    const int k  = blockIdx.x;
    const int j0 = (k * NJOBS) / NCTA;
    const int j1 = ((k + 1) * NJOBS) / NCTA;
    const int n  = j1 - j0;                      // 27 or 28

    auto issue_job = [&](int jj) {
        const int tile2 = jj >> 3, c2 = jj & 7;
        const int bt2 = tile2 >> 2;
        const int t2 = bt2 & 15, b2 = bt2 >> 4;
        const __half* src = g_B + (size_t)((b2 * S_ + t2 * TT) + c2 * 4) * L_ * H_;
        const uint32_t dst = sm_u + (uint32_t)(OFFH_B0 + (jj % 3) * NH_BUF) * 2u;
        #pragma unroll
        for (int q = 0; q < 5; ++q) {
            const int task = tid + q * 256;      // 1280 x 16B
            const int r = task >> 4, seg = task & 15;
            cp16cg(dst + (uint32_t)(r * STRDH + seg * 8) * 2u, src + r * H_ + seg * 8);
        }
    };
    issue_job(j0);
    CP_COMMIT();
    issue_job(j0 + 1);
    CP_COMMIT();

    // ldmatrix base addresses (fixed all session)
    uint32_t a_base[2];
    #pragma unroll
    for (int i = 0; i < 2; ++i) {
        const int row = warp_m * 32 + i * 16 + (lane & 15);
        a_base[i] = sm_u + (uint32_t)(row * STRDH + ((lane >> 4) << 3)) * 2u;
    }
    uint32_t b_off[2];
    #pragma unroll
    for (int jp = 0; jp < 2; ++jp) {
        const int row = warp_n * 40 + jp * 16 + (lane & 7) + ((lane >> 4) << 3);
        b_off[jp] = (uint32_t)(row * STRDH + (((lane >> 3) & 1) << 3)) * 2u;
    }
    const uint32_t b_off4 =
        (uint32_t)((warp_n * 40 + 32 + (lane & 7)) * STRDH + (((lane >> 3) & 1) << 3)) * 2u;

    const int srcLo = (grp << 2) | ((thr4 & 1) << 1);
    const int srcHi = srcLo + 1;
    const bool selB = (thr4 >> 1) != 0;

    int cur_tile = -1;
    int s0 = 0, t0 = 0;
    size_t bS = 0;

    #pragma unroll 1
    for (int i = 0; i < n; ++i) {
        const int j = j0 + i;
        const int tile = j >> 3, chunk = j & 7;

        if (i == n - 1) { CP_WAIT0(); } else { CP_WAIT1(); }
        __syncthreads();   // job j's B visible; all warps past job j-1

        if (i + 2 < n) {
            issue_job(j + 2);
            CP_COMMIT();
        }

        if (tile != cur_tile) {                  // uniform branch per CTA
            cur_tile = tile;
            const int s  = tile & 3;
            const int bt = tile >> 2;
            const int t  = bt & 15;
            const int b  = bt >> 4;
            s0 = s * TM;  t0 = t * TT;  bS = (size_t)b * S_;

            const __half* gA = g_A + ((size_t)b * S_ + s0) * H_;
            #pragma unroll
            for (int q = 0; q < 8; ++q) {        // 2048 x 16B LDG->STS
                const int task = tid + q * 256;
                const int r = task >> 4, seg = task & 15;
                const uint4 v = *(const uint4*)(gA + r * H_ + seg * 8);
                *(uint4*)(smc + (size_t)(r * STRDH + seg * 8) * 2) = v;
            }
            for (int ii = tid; ii < TM * L_; ii += 256) {
                const int l = ii >> 7, r = ii & 127;
                sR1[r * R1STR + l] = g_r1[((size_t)b * L_ + l) * S_ + s0 + r];
            }
            __syncthreads();                     // A + r1 ready
        }

        const uint32_t bb = sm_u + (uint32_t)(OFFH_B0 + (j % 3) * NH_BUF) * 2u;
        float acc[2][5][4];
        #pragma unroll
        for (int ii = 0; ii < 2; ++ii)
            #pragma unroll
            for (int jj = 0; jj < 5; ++jj)
                #pragma unroll
                for (int q = 0; q < 4; ++q) acc[ii][jj][q] = 0.f;

        #pragma unroll
        for (int k16 = 0; k16 < 8; ++k16) {
            const uint32_t koff = (uint32_t)(k16 * 32);
            uint32_t af[2][4];
            ldsm4(af[0][0], af[0][1], af[0][2], af[0][3], a_base[0] + koff);
            ldsm4(af[1][0], af[1][1], af[1][2], af[1][3], a_base[1] + koff);
            uint32_t bf[5][2];
            ldsm4(bf[0][0], bf[0][1], bf[1][0], bf[1][1], bb + b_off[0] + koff);
            ldsm4(bf[2][0], bf[2][1], bf[3][0], bf[3][1], bb + b_off[1] + koff);
            ldsm2(bf[4][0], bf[4][1], bb + b_off4 + koff);
            #pragma unroll
            for (int ii = 0; ii < 2; ++ii)
                #pragma unroll
                for (int jj = 0; jj < 5; ++jj)
                    mma_f16(acc[ii][jj][0], acc[ii][jj][1], acc[ii][jj][2], acc[ii][jj][3],
                            af[ii][0], af[ii][1], af[ii][2], af[ii][3], bf[jj][0], bf[jj][1]);
        }

        // ---- epilogue: scale by r1, shuffle-pair, STG.128 ----
        #pragma unroll
        for (int ii = 0; ii < 2; ++ii) {
            const int rowl = warp_m * 32 + ii * 16 + grp;
            float* orow0 = out + ((bS + s0 + rowl) * S_ + t0 + chunk * 4) * L_;
            float* orow1 = orow0 + (size_t)8 * S_ * L_;

            float2 v0[5], v1r[5];
            #pragma unroll
            for (int jj = 0; jj < 5; ++jj) {
                const int c = warp_n * 40 + jj * 8 + 2 * thr4;  // c = ts*20 + l, l even
                const int l = c - (c / 20) * 20;
                const float2 ra = *(const float2*)&sR1[rowl * R1STR + l];
                const float2 rb = *(const float2*)&sR1[(rowl + 8) * R1STR + l];
                v0[jj].x  = acc[ii][jj][0] * ra.x;  v0[jj].y  = acc[ii][jj][1] * ra.y;
                v1r[jj].x = acc[ii][jj][2] * rb.x;  v1r[jj].y = acc[ii][jj][3] * rb.y;
            }
            #pragma unroll
            for (int p = 0; p < 2; ++p) {
                {
                    float ax = __shfl_sync(0xffffffffu, v0[2*p].x,   srcLo);
                    float ay = __shfl_sync(0xffffffffu, v0[2*p].y,   srcLo);
                    float bx = __shfl_sync(0xffffffffu, v0[2*p+1].x, srcLo);
                    float by = __shfl_sync(0xffffffffu, v0[2*p+1].y, srcLo);
                    float4 o;
                    o.x = selB ? bx : ax;  o.y = selB ? by : ay;
                    ax = __shfl_sync(0xffffffffu, v0[2*p].x,   srcHi);
                    ay = __shfl_sync(0xffffffffu, v0[2*p].y,   srcHi);
                    bx = __shfl_sync(0xffffffffu, v0[2*p+1].x, srcHi);
                    by = __shfl_sync(0xffffffffu, v0[2*p+1].y, srcHi);
                    o.z = selB ? bx : ax;  o.w = selB ? by : ay;
                    *(float4*)(orow0 + warp_n * 40 + p * 16 + 4 * thr4) = o;
                }
                {
                    float ax = __shfl_sync(0xffffffffu, v1r[2*p].x,   srcLo);
                    float ay = __shfl_sync(0xffffffffu, v1r[2*p].y,   srcLo);
                    float bx = __shfl_sync(0xffffffffu, v1r[2*p+1].x, srcLo);
                    float by = __shfl_sync(0xffffffffu, v1r[2*p+1].y, srcLo);
                    float4 o;
                    o.x = selB ? bx : ax;  o.y = selB ? by : ay;
                    ax = __shfl_sync(0xffffffffu, v1r[2*p].x,   srcHi);
                    ay = __shfl_sync(0xffffffffu, v1r[2*p].y,   srcHi);
                    bx = __shfl_sync(0xffffffffu, v1r[2*p+1].x, srcHi);
                    by = __shfl_sync(0xffffffffu, v1r[2*p+1].y, srcHi);
                    o.z = selB ? bx : ax;  o.w = selB ? by : ay;
                    *(float4*)(orow1 + warp_n * 40 + p * 16 + 4 * thr4) = o;
                }
            }
            *(float2*)(orow0 + warp_n * 40 + 32 + 2 * thr4) = v0[4];
            *(float2*)(orow1 + warp_n * 40 + 32 + 2 * thr4) = v1r[4];
        }
    }
}

// ---------------- launch ----------------
extern "C" void kernel_launch(void* const* d_in, const int* in_sizes, int n_in,
                              void* d_out, int out_size) {
    (void)in_sizes; (void)n_in; (void)out_size;
    const float* v1 = (const float*)d_in[0];   // (16, 512, 128)
    const float* v2 = (const float*)d_in[1];   // (16, 512, 128)
    const float* w  = (const float*)d_in[2];   // (20, 128)
    float* out = (float*)d_out;                // (16, 512, 512, 20)

    cudaFuncSetAttribute(match_kernel, cudaFuncAttributeMaxDynamicSharedMemorySize, SMEM_BYTES);

    dim3 pgrid((B_ * S_ * 32) / 256, 2);       // y=0: v1/r1/A, y=1: v2 -> B
    prep_kernel<<<pgrid, 256>>>(v1, v2, w);

    match_kernel<<<NCTA, 256, SMEM_BYTES>>>(out);   // persistent, balanced job ranges
}